// round 14
// baseline (speedup 1.0000x reference)
#include <cuda_runtime.h>
#include <cstdint>

#define N_      16384
#define K_      64
#define F_      2048
#define NCHUNK  4            // column chunks of 512 floats
#define CHUNK   512
#define TPB     128          // each thread owns 4 floats (16B) of the chunk
#define S_      16           // row segments per cluster
#define AB_     256          // assign blocks in setup_k
#define PB_     256          // prep blocks in setup_k
#define ALPHA_F 1.0f
#define GAMMA_F 1.0f

// ---- scratch (static device globals: allocation-free, zero-initialized) ----
__device__ int   g_rows[K_ * N_];        // per-cluster member row lists
__device__ int   g_cnt[K_];              // member counts (reset by main_k)
__device__ float g_rs[K_];               // pairwise dist row-sums (reset by main_k)
__device__ int   g_pdone[K_];            // prep arrival (self-reset)
__device__ float g_ak[K_];               // cw[k] / (rs[k]+alpha)
__device__ float g_invden[K_];           // 1 / (rs[k]+alpha)
__device__ float g_sx[K_ * F_];          // atomic column-sum accumulators
__device__ int   g_done[K_ * NCHUNK];    // per-(k,chunk) epilogue arrival (self-reset)
__device__ int   g_kdone[K_];            // per-k global arrival (self-reset)

// ---------------------------------------------------------------------------
// setup_k: ONE kernel, two independent block families (unchanged, known-good).
// ---------------------------------------------------------------------------
__global__ void __launch_bounds__(256) setup_k(const float* __restrict__ C,
                                               const float* __restrict__ cw,
                                               const float* __restrict__ labels,
                                               float* __restrict__ loss) {
    int b = blockIdx.x, tid = threadIdx.x;
    if (b < AB_) {
        int t = b * 256 + tid;                       // 65536 threads
        reinterpret_cast<float2*>(g_sx)[t] = make_float2(0.f, 0.f);

        int row = t >> 2, part = t & 3;
        const float4* p =
            reinterpret_cast<const float4*>(labels + row * K_) + part * 4;
        float acc = 0.f;
#pragma unroll
        for (int j = 0; j < 4; j++) {
            float4 v = p[j];
            float base = (float)(part * 16 + j * 4);
            acc += v.x * base + v.y * (base + 1.f)
                 + v.z * (base + 2.f) + v.w * (base + 3.f);
        }
        acc += __shfl_xor_sync(0xFFFFFFFFu, acc, 1);
        acc += __shfl_xor_sync(0xFFFFFFFFu, acc, 2);
        if (part == 0) {
            int k = (int)(acc + 0.5f);
            int slot = atomicAdd(&g_cnt[k], 1);
            g_rows[k * N_ + slot] = row;
            loss[row] = 0.f;
        }
    } else {
        int pb = b - AB_;
        int k = pb >> 2, c = pb & 3;
        int col = c * 512 + 2 * tid;
        float2 a = *reinterpret_cast<const float2*>(C + k * F_ + col);
        float acc = 0.f;
#pragma unroll 8
        for (int j = 0; j < K_; j++) {
            float2 bv = *reinterpret_cast<const float2*>(C + j * F_ + col);
            float d0 = a.x - bv.x, d1 = a.y - bv.y;
            acc += d0 * d0 + d1 * d1;
        }
#pragma unroll
        for (int o = 16; o; o >>= 1)
            acc += __shfl_xor_sync(0xFFFFFFFFu, acc, o);
        __shared__ float sw_[8];
        int w = tid >> 5, l = tid & 31;
        if (l == 0) sw_[w] = acc;
        __syncthreads();
        if (tid == 0) {
            float bs = 0.f;
#pragma unroll
            for (int i = 0; i < 8; i++) bs += sw_[i];
            atomicAdd(&g_rs[k], bs);
            __threadfence();
            if (atomicAdd(&g_pdone[k], 1) == 3) {
                float rs = *(volatile float*)&g_rs[k];
                float inv = 1.f / (rs + ALPHA_F);
                g_invden[k] = inv;
                g_ak[k]     = cw[k] * inv;
                g_pdone[k]  = 0;
            }
        }
    }
}

// ---------------------------------------------------------------------------
// main_k: MAX-OCCUPANCY design. Block (chunk c, cluster k, segment s),
// 128 threads, thread owns ONE float4. No smem staging, no reg pipeline —
// ~40 regs -> 12+ blocks/SM (48-64 warps) and warp count hides DRAM latency.
// 2-row unroll gives MLP=2/warp. Loss reduce: 3 shuffle levels to 4 residue
// classes, then a 4-lane same-address REDG (no return -> no scoreboard wait).
// ---------------------------------------------------------------------------
__global__ void __launch_bounds__(TPB) main_k(const float* __restrict__ X,
                                              const float* __restrict__ C,
                                              float* __restrict__ out) {
    __shared__ int amLast;

    int c   = blockIdx.x;
    int k   = blockIdx.y;
    int seg = blockIdx.z;
    int tid = threadIdx.x;
    int l   = tid & 31;
    int col = c * CHUNK + 4 * tid;

    float4 ck = *reinterpret_cast<const float4*>(C + k * F_ + col);
    float4 ac = make_float4(0.f, 0.f, 0.f, 0.f);

    int   cnt  = g_cnt[k];
    float invd = g_invden[k];
    float* loss = out;                          // loss at out[0..N)

    int r0 = (cnt * seg) / S_;
    int r1 = (cnt * (seg + 1)) / S_;
    const int* rl = g_rows + k * N_;

    int r = r0;
    for (; r + 2 <= r1; r += 2) {
        int n0 = __ldg(rl + r), n1 = __ldg(rl + r + 1);
        float4 x0 = *reinterpret_cast<const float4*>(X + (size_t)n0 * F_ + col);
        float4 x1 = *reinterpret_cast<const float4*>(X + (size_t)n1 * F_ + col);

        float a0 = x0.x - ck.x, b0 = x0.y - ck.y;
        float c0 = x0.z - ck.z, d0 = x0.w - ck.w;
        float a1 = x1.x - ck.x, b1 = x1.y - ck.y;
        float c1 = x1.z - ck.z, d1 = x1.w - ck.w;
        float s0 = a0 * a0 + b0 * b0 + c0 * c0 + d0 * d0;
        float s1 = a1 * a1 + b1 * b1 + c1 * c1 + d1 * d1;
        ac.x += x0.x + x1.x; ac.y += x0.y + x1.y;
        ac.z += x0.z + x1.z; ac.w += x0.w + x1.w;

        // two independent 3-level reduces (interleaved chains)
#pragma unroll
        for (int o = 16; o >= 4; o >>= 1) {
            s0 += __shfl_xor_sync(0xFFFFFFFFu, s0, o);
            s1 += __shfl_xor_sync(0xFFFFFFFFu, s1, o);
        }
        // lanes 0..3 each hold one residue-class partial; 4-lane REDG
        if (l < 4) {
            atomicAdd(loss + n0, s0 * invd);
            atomicAdd(loss + n1, s1 * invd);
        }
    }
    if (r < r1) {                               // tail row
        int n0 = __ldg(rl + r);
        float4 x0 = *reinterpret_cast<const float4*>(X + (size_t)n0 * F_ + col);
        float a0 = x0.x - ck.x, b0 = x0.y - ck.y;
        float c0 = x0.z - ck.z, d0 = x0.w - ck.w;
        float s0 = a0 * a0 + b0 * b0 + c0 * c0 + d0 * d0;
        ac.x += x0.x; ac.y += x0.y; ac.z += x0.z; ac.w += x0.w;
#pragma unroll
        for (int o = 16; o >= 4; o >>= 1)
            s0 += __shfl_xor_sync(0xFFFFFFFFu, s0, o);
        if (l < 4) atomicAdd(loss + n0, s0 * invd);
    }

    // accumulate segment partials into g_sx
    float* sx = g_sx + k * F_ + col;
    atomicAdd(sx + 0, ac.x); atomicAdd(sx + 1, ac.y);
    atomicAdd(sx + 2, ac.z); atomicAdd(sx + 3, ac.w);

    // fence + block barrier BEFORE arrival (R12 race fix — keep)
    __threadfence();
    __syncthreads();
    if (tid == 0)
        amLast = (atomicAdd(&g_done[k * NCHUNK + c], 1) == S_ - 1);
    __syncthreads();
    if (amLast) {
        float4 s0 = __ldcg(reinterpret_cast<const float4*>(sx));
        float ga = GAMMA_F * g_ak[k];
        float fc = (float)cnt;
        float4 o;
        o.x = ck.x - ga * (s0.x - fc * ck.x);
        o.y = ck.y - ga * (s0.y - fc * ck.y);
        o.z = ck.z - ga * (s0.z - fc * ck.z);
        o.w = ck.w - ga * (s0.w - fc * ck.w);
        *reinterpret_cast<float4*>(out + N_ + k * F_ + col) = o;
        if (tid == 0) g_done[k * NCHUNK + c] = 0;   // reset for graph replay
    }

    // globally-last block of cluster k resets per-k state for next replay.
    if (tid == 0) {
        if (atomicAdd(&g_kdone[k], 1) == S_ * NCHUNK - 1) {
            g_kdone[k] = 0;
            g_cnt[k]   = 0;
            g_rs[k]    = 0.f;
        }
    }
}

extern "C" void kernel_launch(void* const* d_in, const int* in_sizes, int n_in,
                              void* d_out, int out_size) {
    const float* X  = (const float*)d_in[0];   // features [N,F]
    const float* L  = (const float*)d_in[1];   // labels   [N,K] one-hot
    const float* C  = (const float*)d_in[2];   // cluster  [K,F]
    const float* CW = (const float*)d_in[3];   // class_weight [K]
    float* out = (float*)d_out;                // [loss(N) | new_cluster(K*F)]

    setup_k <<<AB_ + PB_, 256>>>(C, CW, L, out);
    main_k  <<<dim3(NCHUNK, K_, S_), TPB>>>(X, C, out);
}

// round 15
// speedup vs baseline: 1.2878x; 1.2878x over previous
#include <cuda_runtime.h>
#include <cstdint>

#define N_      16384
#define K_      64
#define F_      2048
#define NCHUNK  4            // column chunks of 512 floats
#define CHUNK   512
#define TPB     128
#define S_      8            // row segments per cluster
#define AB_     256          // assign blocks
#define PB_     256          // prep blocks
#define KB_     64           // bucket blocks
#define ALPHA_F 1.0f
#define GAMMA_F 1.0f

// ---- scratch (static device globals: allocation-free, zero-initialized) ----
__device__ int   g_idx[N_];              // per-row cluster id
__device__ int   g_rows[K_ * N_];        // per-cluster member lists (SORTED)
__device__ int   g_cnt[K_];              // member counts (rewritten each call)
__device__ float g_rs[K_];               // pairwise dist row-sums (reset by main_k)
__device__ int   g_pdone[K_];            // prep arrival (self-reset)
__device__ int   g_adone;                // assign-family arrival (self-reset)
__device__ int   g_bdone;                // bucket gate-pass counter (self-reset)
__device__ float g_ak[K_];               // cw[k] / (rs[k]+alpha)
__device__ float g_invden[K_];           // 1 / (rs[k]+alpha)
__device__ float g_sx[K_ * F_];          // atomic column-sum accumulators
__device__ int   g_done[K_ * NCHUNK];    // epilogue arrival (self-reset)
__device__ int   g_kdone[K_];            // per-k global arrival (self-reset)

// ---------------------------------------------------------------------------
// setup_k: ONE kernel, three block families (all 576 blocks co-resident, so
// the bucket family may spin-gate on the assign family without deadlock).
//  [0,256):   assign — idx from exact one-hot, writes g_idx; zeros g_sx+loss.
//  [256,512): prep — partial sum_j ||c_k-c_j||^2 -> g_rs; last computes ak.
//  [512,576): bucket — spin until all assign blocks done, then deterministic
//             ballot compaction of g_idx into SORTED per-cluster row lists.
// ---------------------------------------------------------------------------
__global__ void __launch_bounds__(256) setup_k(const float* __restrict__ C,
                                               const float* __restrict__ cw,
                                               const float* __restrict__ labels,
                                               float* __restrict__ loss) {
    int b = blockIdx.x, tid = threadIdx.x;
    if (b < AB_) {
        // ---------------- assign family ----------------
        int t = b * 256 + tid;                       // 65536 threads
        reinterpret_cast<float2*>(g_sx)[t] = make_float2(0.f, 0.f);

        int row = t >> 2, part = t & 3;
        const float4* p =
            reinterpret_cast<const float4*>(labels + row * K_) + part * 4;
        float acc = 0.f;
#pragma unroll
        for (int j = 0; j < 4; j++) {
            float4 v = p[j];
            float base = (float)(part * 16 + j * 4);
            acc += v.x * base + v.y * (base + 1.f)
                 + v.z * (base + 2.f) + v.w * (base + 3.f);
        }
        acc += __shfl_xor_sync(0xFFFFFFFFu, acc, 1);
        acc += __shfl_xor_sync(0xFFFFFFFFu, acc, 2);
        if (part == 0) {
            g_idx[row] = (int)(acc + 0.5f);
            loss[row] = 0.f;
        }
        __syncthreads();
        if (tid == 0) { __threadfence(); atomicAdd(&g_adone, 1); }
    } else if (b < AB_ + PB_) {
        // ---------------- prep family ----------------
        int pb = b - AB_;
        int k = pb >> 2, c = pb & 3;
        int col = c * 512 + 2 * tid;
        float2 a = *reinterpret_cast<const float2*>(C + k * F_ + col);
        float acc = 0.f;
#pragma unroll 8
        for (int j = 0; j < K_; j++) {
            float2 bv = *reinterpret_cast<const float2*>(C + j * F_ + col);
            float d0 = a.x - bv.x, d1 = a.y - bv.y;
            acc += d0 * d0 + d1 * d1;
        }
#pragma unroll
        for (int o = 16; o; o >>= 1)
            acc += __shfl_xor_sync(0xFFFFFFFFu, acc, o);
        __shared__ float sw_[8];
        int w = tid >> 5, l = tid & 31;
        if (l == 0) sw_[w] = acc;
        __syncthreads();
        if (tid == 0) {
            float bs = 0.f;
#pragma unroll
            for (int i = 0; i < 8; i++) bs += sw_[i];
            atomicAdd(&g_rs[k], bs);
            __threadfence();
            if (atomicAdd(&g_pdone[k], 1) == 3) {
                float rs = *(volatile float*)&g_rs[k];
                float inv = 1.f / (rs + ALPHA_F);
                g_invden[k] = inv;
                g_ak[k]     = cw[k] * inv;
                g_pdone[k]  = 0;
            }
        }
    } else {
        // ---------------- bucket family (sorted compaction) ----------------
        int k = b - (AB_ + PB_);
        if (tid == 0) {
            while (*(volatile int*)&g_adone != AB_) __nanosleep(64);
            if (atomicAdd(&g_bdone, 1) == KB_ - 1) {  // last to pass the gate
                g_adone = 0;                          // safe: all passed
                g_bdone = 0;
            }
        }
        __syncthreads();
        __threadfence();

        int w = tid >> 5, l = tid & 31;
        __shared__ int wcnt[8][4];
        unsigned lmask = (1u << l) - 1u;
        int base = 0;
        for (int t0 = 0; t0 < N_; t0 += 1024) {
            int4 v = __ldcg(reinterpret_cast<const int4*>(g_idx + t0 + 4 * tid));
            int pred[4] = { v.x == k, v.y == k, v.z == k, v.w == k };
            unsigned bb[4];
#pragma unroll
            for (int e = 0; e < 4; e++) {
                bb[e] = __ballot_sync(0xFFFFFFFFu, pred[e]);
                if (l == 0) wcnt[w][e] = __popc(bb[e]);
            }
            __syncthreads();
            int run = 0;
#pragma unroll
            for (int e = 0; e < 4; e++) {
                int woff = 0, tote = 0;
#pragma unroll
                for (int j = 0; j < 8; j++) {
                    int cc = wcnt[j][e];
                    tote += cc;
                    if (j < w) woff += cc;
                }
                if (pred[e])
                    g_rows[k * N_ + base + run + woff + __popc(bb[e] & lmask)]
                        = t0 + 4 * tid + e;
                run += tote;
            }
            base += run;
            __syncthreads();
        }
        if (tid == 0) g_cnt[k] = base;
    }
}

// ---------------------------------------------------------------------------
// process8: R7's proven 8-row distance + 16-shuffle multi-row loss reduce.
// ---------------------------------------------------------------------------
__device__ __forceinline__ void process8(const float4* x, const int* srows, int i,
                                         float4 ck, float& ax, float& ay,
                                         float& az, float& aw,
                                         float invd, float* loss, int l) {
    float s[8];
#pragma unroll
    for (int j = 0; j < 8; j++) {
        float dx = x[j].x - ck.x, dy = x[j].y - ck.y;
        float dz = x[j].z - ck.z, dw = x[j].w - ck.w;
        s[j] = dx * dx + dy * dy + dz * dz + dw * dw;
        ax += x[j].x; ay += x[j].y; az += x[j].z; aw += x[j].w;
    }
    float cc[4];
#pragma unroll
    for (int p = 0; p < 4; p++) {
        float t0 = __shfl_xor_sync(0xFFFFFFFFu, s[2 * p], 16);
        float t1 = __shfl_xor_sync(0xFFFFFFFFu, s[2 * p + 1], 16);
        cc[p] = (l & 16) ? (s[2 * p + 1] + t1) : (s[2 * p] + t0);
    }
    float dd_[2];
#pragma unroll
    for (int p = 0; p < 2; p++) {
        float t0 = __shfl_xor_sync(0xFFFFFFFFu, cc[2 * p], 8);
        float t1 = __shfl_xor_sync(0xFFFFFFFFu, cc[2 * p + 1], 8);
        dd_[p] = (l & 8) ? (cc[2 * p + 1] + t1) : (cc[2 * p] + t0);
    }
    float t0 = __shfl_xor_sync(0xFFFFFFFFu, dd_[0], 4);
    float t1 = __shfl_xor_sync(0xFFFFFFFFu, dd_[1], 4);
    float e  = (l & 4) ? (dd_[1] + t1) : (dd_[0] + t0);
    e += __shfl_xor_sync(0xFFFFFFFFu, e, 2);
    e += __shfl_xor_sync(0xFFFFFFFFu, e, 1);
    if ((l & 3) == 0) {
        int mm = l >> 2;
        int j = ((mm & 1) << 2) | (mm & 2) | (mm >> 2);   // bit-reverse3
        atomicAdd(loss + srows[i + j], e * invd);
    }
}

// ---------------------------------------------------------------------------
// main_k: R7's depth-8 register pipeline (measured best: 31.6us) + fused
// atomic-g_sx epilogue with the R12 race fix. Sorted row lists from setup.
// ---------------------------------------------------------------------------
__global__ void __launch_bounds__(TPB) main_k(const float* __restrict__ X,
                                              const float* __restrict__ C,
                                              float* __restrict__ out) {
    __shared__ int srows[TPB];
    __shared__ int amLast;

    int c   = blockIdx.x;
    int k   = blockIdx.y;
    int seg = blockIdx.z;
    int tid = threadIdx.x;
    int l   = tid & 31;
    int col = c * CHUNK + 4 * tid;

    float4 ck = *reinterpret_cast<const float4*>(C + k * F_ + col);
    float ax = 0.f, ay = 0.f, az = 0.f, aw = 0.f;
    int   cnt  = g_cnt[k];
    float invd = g_invden[k];
    float* loss = out;                          // loss at out[0..N)

    int r0 = (cnt * seg) / S_;
    int r1 = (cnt * (seg + 1)) / S_;
    const int* rl = g_rows + k * N_;

    for (int rb = r0; rb < r1; rb += TPB) {
        int m = min(TPB, r1 - rb);
        if (tid < m) srows[tid] = rl[rb + tid];
        __syncthreads();
        int i = 0;
        if (m >= 8) {
            float4 x[8];
#pragma unroll
            for (int j = 0; j < 8; j++)
                x[j] = *reinterpret_cast<const float4*>(
                    X + (size_t)srows[j] * F_ + col);
#pragma unroll 2
            for (i = 0; i + 16 <= m; i += 8) {
                float4 y[8];
#pragma unroll
                for (int j = 0; j < 8; j++)
                    y[j] = *reinterpret_cast<const float4*>(
                        X + (size_t)srows[i + 8 + j] * F_ + col);
                process8(x, srows, i, ck, ax, ay, az, aw, invd, loss, l);
#pragma unroll
                for (int j = 0; j < 8; j++) x[j] = y[j];
            }
            process8(x, srows, i, ck, ax, ay, az, aw, invd, loss, l);
            i += 8;
        }
        for (; i < m; i++) {                    // tail rows
            float4 x = *reinterpret_cast<const float4*>(
                X + (size_t)srows[i] * F_ + col);
            float dx = x.x - ck.x, dy = x.y - ck.y;
            float dz = x.z - ck.z, dw = x.w - ck.w;
            float s = dx * dx + dy * dy + dz * dz + dw * dw;
            ax += x.x; ay += x.y; az += x.z; aw += x.w;
#pragma unroll
            for (int o = 16; o; o >>= 1)
                s += __shfl_xor_sync(0xFFFFFFFFu, s, o);
            if (l == 0) atomicAdd(loss + srows[i], s * invd);
        }
        __syncthreads();
    }

    // accumulate segment partials into g_sx
    float* sx = g_sx + k * F_ + col;
    atomicAdd(sx + 0, ax); atomicAdd(sx + 1, ay);
    atomicAdd(sx + 2, az); atomicAdd(sx + 3, aw);

    // fence + block barrier BEFORE arrival (R12 race fix — keep)
    __threadfence();
    __syncthreads();
    if (tid == 0)
        amLast = (atomicAdd(&g_done[k * NCHUNK + c], 1) == S_ - 1);
    __syncthreads();
    if (amLast) {
        float4 s0 = __ldcg(reinterpret_cast<const float4*>(sx));
        float ga = GAMMA_F * g_ak[k];
        float fc = (float)cnt;
        float4 o;
        o.x = ck.x - ga * (s0.x - fc * ck.x);
        o.y = ck.y - ga * (s0.y - fc * ck.y);
        o.z = ck.z - ga * (s0.z - fc * ck.z);
        o.w = ck.w - ga * (s0.w - fc * ck.w);
        *reinterpret_cast<float4*>(out + N_ + k * F_ + col) = o;
        if (tid == 0) g_done[k * NCHUNK + c] = 0;   // reset for graph replay
    }

    // globally-last block of cluster k resets per-k state for next replay.
    if (tid == 0) {
        if (atomicAdd(&g_kdone[k], 1) == S_ * NCHUNK - 1) {
            g_kdone[k] = 0;
            g_rs[k]    = 0.f;       // g_cnt rewritten fresh by bucket family
        }
    }
}

extern "C" void kernel_launch(void* const* d_in, const int* in_sizes, int n_in,
                              void* d_out, int out_size) {
    const float* X  = (const float*)d_in[0];   // features [N,F]
    const float* L  = (const float*)d_in[1];   // labels   [N,K] one-hot
    const float* C  = (const float*)d_in[2];   // cluster  [K,F]
    const float* CW = (const float*)d_in[3];   // class_weight [K]
    float* out = (float*)d_out;                // [loss(N) | new_cluster(K*F)]

    setup_k <<<AB_ + PB_ + KB_, 256>>>(C, CW, L, out);
    main_k  <<<dim3(NCHUNK, K_, S_), TPB>>>(X, C, out);
}

// round 16
// speedup vs baseline: 1.3799x; 1.0716x over previous
#include <cuda_runtime.h>
#include <cstdint>

#define N_      16384
#define K_      64
#define F_      2048
#define NCHUNK  4            // column chunks of 512 floats
#define CHUNK   512
#define TPB     128
#define S_      8            // row segments per cluster
#define AB_     256          // assign blocks in setup_k
#define PB_     256          // prep blocks in setup_k
#define ALPHA_F 1.0f
#define GAMMA_F 1.0f

// ---- scratch (static device globals: allocation-free, zero-initialized) ----
__device__ int   g_rows[K_ * N_];        // per-cluster member lists (arrival order)
__device__ int   g_cnt[K_];              // member counts (reset by main_k)
__device__ float g_rs[K_];               // pairwise dist row-sums (reset by main_k)
__device__ int   g_pdone[K_];            // prep arrival (self-reset)
__device__ float g_ak[K_];               // cw[k] / (rs[k]+alpha)
__device__ float g_invden[K_];           // 1 / (rs[k]+alpha)
__device__ float g_sx[S_ * K_ * F_];     // EXCLUSIVE per-(seg,k) column sums (16MB)
__device__ int   g_done[K_ * NCHUNK];    // epilogue arrival (self-reset)
__device__ int   g_kdone[K_];            // per-k global arrival (self-reset)

// ---------------------------------------------------------------------------
// setup_k: ONE kernel, two independent block families (R12-proven).
//  [0,256):   assign — idx from exact one-hot (sum v[i]*i), slot via
//             atomicAdd(g_cnt), zero the loss region. (g_sx needs no zeroing
//             now: every cell is written unconditionally by its owner block.)
//  [256,512): prep — partial sum_j ||c_k-c_j||^2 -> g_rs; last computes ak.
// ---------------------------------------------------------------------------
__global__ void __launch_bounds__(256) setup_k(const float* __restrict__ C,
                                               const float* __restrict__ cw,
                                               const float* __restrict__ labels,
                                               float* __restrict__ loss) {
    int b = blockIdx.x, tid = threadIdx.x;
    if (b < AB_) {
        int t = b * 256 + tid;                       // 65536 threads
        int row = t >> 2, part = t & 3;
        const float4* p =
            reinterpret_cast<const float4*>(labels + row * K_) + part * 4;
        float acc = 0.f;
#pragma unroll
        for (int j = 0; j < 4; j++) {
            float4 v = p[j];
            float base = (float)(part * 16 + j * 4);
            acc += v.x * base + v.y * (base + 1.f)
                 + v.z * (base + 2.f) + v.w * (base + 3.f);
        }
        acc += __shfl_xor_sync(0xFFFFFFFFu, acc, 1);
        acc += __shfl_xor_sync(0xFFFFFFFFu, acc, 2);
        if (part == 0) {
            int k = (int)(acc + 0.5f);
            int slot = atomicAdd(&g_cnt[k], 1);
            g_rows[k * N_ + slot] = row;
            loss[row] = 0.f;
        }
    } else {
        int pb = b - AB_;
        int k = pb >> 2, c = pb & 3;
        int col = c * 512 + 2 * tid;
        float2 a = *reinterpret_cast<const float2*>(C + k * F_ + col);
        float acc = 0.f;
#pragma unroll 8
        for (int j = 0; j < K_; j++) {
            float2 bv = *reinterpret_cast<const float2*>(C + j * F_ + col);
            float d0 = a.x - bv.x, d1 = a.y - bv.y;
            acc += d0 * d0 + d1 * d1;
        }
#pragma unroll
        for (int o = 16; o; o >>= 1)
            acc += __shfl_xor_sync(0xFFFFFFFFu, acc, o);
        __shared__ float sw_[8];
        int w = tid >> 5, l = tid & 31;
        if (l == 0) sw_[w] = acc;
        __syncthreads();
        if (tid == 0) {
            float bs = 0.f;
#pragma unroll
            for (int i = 0; i < 8; i++) bs += sw_[i];
            atomicAdd(&g_rs[k], bs);
            __threadfence();
            if (atomicAdd(&g_pdone[k], 1) == 3) {
                float rs = *(volatile float*)&g_rs[k];
                float inv = 1.f / (rs + ALPHA_F);
                g_invden[k] = inv;
                g_ak[k]     = cw[k] * inv;
                g_pdone[k]  = 0;
            }
        }
    }
}

// ---------------------------------------------------------------------------
// process8: 8-row distance + 16-shuffle multi-row loss reduce (R6-proven).
// ---------------------------------------------------------------------------
__device__ __forceinline__ void process8(const float4* x, const int* srows, int i,
                                         float4 ck, float& ax, float& ay,
                                         float& az, float& aw,
                                         float invd, float* loss, int l) {
    float s[8];
#pragma unroll
    for (int j = 0; j < 8; j++) {
        float dx = x[j].x - ck.x, dy = x[j].y - ck.y;
        float dz = x[j].z - ck.z, dw = x[j].w - ck.w;
        s[j] = dx * dx + dy * dy + dz * dz + dw * dw;
        ax += x[j].x; ay += x[j].y; az += x[j].z; aw += x[j].w;
    }
    float cc[4];
#pragma unroll
    for (int p = 0; p < 4; p++) {
        float t0 = __shfl_xor_sync(0xFFFFFFFFu, s[2 * p], 16);
        float t1 = __shfl_xor_sync(0xFFFFFFFFu, s[2 * p + 1], 16);
        cc[p] = (l & 16) ? (s[2 * p + 1] + t1) : (s[2 * p] + t0);
    }
    float dd_[2];
#pragma unroll
    for (int p = 0; p < 2; p++) {
        float t0 = __shfl_xor_sync(0xFFFFFFFFu, cc[2 * p], 8);
        float t1 = __shfl_xor_sync(0xFFFFFFFFu, cc[2 * p + 1], 8);
        dd_[p] = (l & 8) ? (cc[2 * p + 1] + t1) : (cc[2 * p] + t0);
    }
    float t0 = __shfl_xor_sync(0xFFFFFFFFu, dd_[0], 4);
    float t1 = __shfl_xor_sync(0xFFFFFFFFu, dd_[1], 4);
    float e  = (l & 4) ? (dd_[1] + t1) : (dd_[0] + t0);
    e += __shfl_xor_sync(0xFFFFFFFFu, e, 2);
    e += __shfl_xor_sync(0xFFFFFFFFu, e, 1);
    if ((l & 3) == 0) {
        int mm = l >> 2;
        int j = ((mm & 1) << 2) | (mm & 2) | (mm >> 2);   // bit-reverse3
        atomicAdd(loss + srows[i + j], e * invd);
    }
}

// ---------------------------------------------------------------------------
// main_k: R6's depth-8 register pipeline (measured 31.6us). Epilogue now uses
// EXCLUSIVE plain stores into g_sx[seg] (no atomics, no contention), and the
// amLast block per (k,c) folds the S_ segment slices from L2 and writes
// new_cluster. R12 fence+barrier ordering kept for store visibility.
// ---------------------------------------------------------------------------
__global__ void __launch_bounds__(TPB) main_k(const float* __restrict__ X,
                                              const float* __restrict__ C,
                                              float* __restrict__ out) {
    __shared__ int srows[TPB];
    __shared__ int amLast;

    int c   = blockIdx.x;
    int k   = blockIdx.y;
    int seg = blockIdx.z;
    int tid = threadIdx.x;
    int l   = tid & 31;
    int col = c * CHUNK + 4 * tid;

    float4 ck = *reinterpret_cast<const float4*>(C + k * F_ + col);
    float ax = 0.f, ay = 0.f, az = 0.f, aw = 0.f;
    int   cnt  = g_cnt[k];
    float invd = g_invden[k];
    float* loss = out;                          // loss at out[0..N)

    int r0 = (cnt * seg) / S_;
    int r1 = (cnt * (seg + 1)) / S_;
    const int* rl = g_rows + k * N_;

    for (int rb = r0; rb < r1; rb += TPB) {
        int m = min(TPB, r1 - rb);
        if (tid < m) srows[tid] = rl[rb + tid];
        __syncthreads();
        int i = 0;
        if (m >= 8) {
            float4 x[8];
#pragma unroll
            for (int j = 0; j < 8; j++)
                x[j] = *reinterpret_cast<const float4*>(
                    X + (size_t)srows[j] * F_ + col);
#pragma unroll 2
            for (i = 0; i + 16 <= m; i += 8) {
                float4 y[8];
#pragma unroll
                for (int j = 0; j < 8; j++)
                    y[j] = *reinterpret_cast<const float4*>(
                        X + (size_t)srows[i + 8 + j] * F_ + col);
                process8(x, srows, i, ck, ax, ay, az, aw, invd, loss, l);
#pragma unroll
                for (int j = 0; j < 8; j++) x[j] = y[j];
            }
            process8(x, srows, i, ck, ax, ay, az, aw, invd, loss, l);
            i += 8;
        }
        for (; i < m; i++) {                    // tail rows
            float4 x = *reinterpret_cast<const float4*>(
                X + (size_t)srows[i] * F_ + col);
            float dx = x.x - ck.x, dy = x.y - ck.y;
            float dz = x.z - ck.z, dw = x.w - ck.w;
            float s = dx * dx + dy * dy + dz * dz + dw * dw;
            ax += x.x; ay += x.y; az += x.z; aw += x.w;
#pragma unroll
            for (int o = 16; o; o >>= 1)
                s += __shfl_xor_sync(0xFFFFFFFFu, s, o);
            if (l == 0) atomicAdd(loss + srows[i], s * invd);
        }
        __syncthreads();
    }

    // EXCLUSIVE segment-partial store (this block owns this g_sx cell)
    *reinterpret_cast<float4*>(g_sx + ((size_t)seg * K_ + k) * F_ + col)
        = make_float4(ax, ay, az, aw);

    // fence + block barrier BEFORE arrival: all warps' stores ordered before
    // this block's arrival is observable (R12 race fix, kept).
    __threadfence();
    __syncthreads();
    if (tid == 0)
        amLast = (atomicAdd(&g_done[k * NCHUNK + c], 1) == S_ - 1);
    __syncthreads();
    if (amLast) {
        float4 sum = make_float4(0.f, 0.f, 0.f, 0.f);
#pragma unroll
        for (int s = 0; s < S_; s++) {
            float4 v = __ldcg(reinterpret_cast<const float4*>(
                g_sx + ((size_t)s * K_ + k) * F_ + col));
            sum.x += v.x; sum.y += v.y; sum.z += v.z; sum.w += v.w;
        }
        float ga = GAMMA_F * g_ak[k];
        float fc = (float)cnt;
        float4 o;
        o.x = ck.x - ga * (sum.x - fc * ck.x);
        o.y = ck.y - ga * (sum.y - fc * ck.y);
        o.z = ck.z - ga * (sum.z - fc * ck.z);
        o.w = ck.w - ga * (sum.w - fc * ck.w);
        *reinterpret_cast<float4*>(out + N_ + k * F_ + col) = o;
        if (tid == 0) g_done[k * NCHUNK + c] = 0;   // reset for graph replay
    }

    // globally-last block of cluster k resets per-k state for next replay.
    if (tid == 0) {
        if (atomicAdd(&g_kdone[k], 1) == S_ * NCHUNK - 1) {
            g_kdone[k] = 0;
            g_cnt[k]   = 0;
            g_rs[k]    = 0.f;
        }
    }
}

extern "C" void kernel_launch(void* const* d_in, const int* in_sizes, int n_in,
                              void* d_out, int out_size) {
    const float* X  = (const float*)d_in[0];   // features [N,F]
    const float* L  = (const float*)d_in[1];   // labels   [N,K] one-hot
    const float* C  = (const float*)d_in[2];   // cluster  [K,F]
    const float* CW = (const float*)d_in[3];   // class_weight [K]
    float* out = (float*)d_out;                // [loss(N) | new_cluster(K*F)]

    setup_k <<<AB_ + PB_, 256>>>(C, CW, L, out);
    main_k  <<<dim3(NCHUNK, K_, S_), TPB>>>(X, C, out);
}

// round 17
// speedup vs baseline: 1.4406x; 1.0440x over previous
#include <cuda_runtime.h>
#include <cstdint>

#define N_      16384
#define K_      64
#define F_      2048
#define NCHUNK  4            // column chunks of 512 floats
#define CHUNK   512
#define TPB     128
#define S_      8            // row segments per cluster
#define AB_     256          // assign blocks in setup_k
#define PB_     256          // prep blocks in setup_k
#define ALPHA_F 1.0f
#define GAMMA_F 1.0f

// ---- scratch (static device globals: allocation-free, zero-initialized) ----
__device__ int   g_rows[K_ * N_];        // per-cluster member lists (arrival order)
__device__ int   g_cnt[K_];              // member counts (reset by reduce_k)
__device__ float g_rs[K_];               // pairwise dist row-sums (reset by reduce_k)
__device__ int   g_pdone[K_];            // prep arrival (self-reset)
__device__ int   g_rdone[K_];            // reduce arrival (self-reset)
__device__ float g_ak[K_];               // cw[k] / (rs[k]+alpha)
__device__ float g_invden[K_];           // 1 / (rs[k]+alpha)
__device__ float g_sx[S_ * K_ * F_];     // EXCLUSIVE per-(seg,k) column sums

// ---------------------------------------------------------------------------
// setup_k: ONE kernel, two independent block families (R12-proven).
//  [0,256):   assign — idx from exact one-hot (sum v[i]*i), slot via
//             atomicAdd(g_cnt), zero the loss region.
//  [256,512): prep — partial sum_j ||c_k-c_j||^2 -> g_rs; last computes ak.
// ---------------------------------------------------------------------------
__global__ void __launch_bounds__(256) setup_k(const float* __restrict__ C,
                                               const float* __restrict__ cw,
                                               const float* __restrict__ labels,
                                               float* __restrict__ loss) {
    int b = blockIdx.x, tid = threadIdx.x;
    if (b < AB_) {
        int t = b * 256 + tid;                       // 65536 threads
        int row = t >> 2, part = t & 3;
        const float4* p =
            reinterpret_cast<const float4*>(labels + row * K_) + part * 4;
        float acc = 0.f;
#pragma unroll
        for (int j = 0; j < 4; j++) {
            float4 v = p[j];
            float base = (float)(part * 16 + j * 4);
            acc += v.x * base + v.y * (base + 1.f)
                 + v.z * (base + 2.f) + v.w * (base + 3.f);
        }
        acc += __shfl_xor_sync(0xFFFFFFFFu, acc, 1);
        acc += __shfl_xor_sync(0xFFFFFFFFu, acc, 2);
        if (part == 0) {
            int k = (int)(acc + 0.5f);
            int slot = atomicAdd(&g_cnt[k], 1);
            g_rows[k * N_ + slot] = row;
            loss[row] = 0.f;
        }
    } else {
        int pb = b - AB_;
        int k = pb >> 2, c = pb & 3;
        int col = c * 512 + 2 * tid;
        float2 a = *reinterpret_cast<const float2*>(C + k * F_ + col);
        float acc = 0.f;
#pragma unroll 8
        for (int j = 0; j < K_; j++) {
            float2 bv = *reinterpret_cast<const float2*>(C + j * F_ + col);
            float d0 = a.x - bv.x, d1 = a.y - bv.y;
            acc += d0 * d0 + d1 * d1;
        }
#pragma unroll
        for (int o = 16; o; o >>= 1)
            acc += __shfl_xor_sync(0xFFFFFFFFu, acc, o);
        __shared__ float sw_[8];
        int w = tid >> 5, l = tid & 31;
        if (l == 0) sw_[w] = acc;
        __syncthreads();
        if (tid == 0) {
            float bs = 0.f;
#pragma unroll
            for (int i = 0; i < 8; i++) bs += sw_[i];
            atomicAdd(&g_rs[k], bs);
            __threadfence();
            if (atomicAdd(&g_pdone[k], 1) == 3) {
                float rs = *(volatile float*)&g_rs[k];
                float inv = 1.f / (rs + ALPHA_F);
                g_invden[k] = inv;
                g_ak[k]     = cw[k] * inv;
                g_pdone[k]  = 0;
            }
        }
    }
}

// ---------------------------------------------------------------------------
// process8: 8-row distance + 16-shuffle multi-row loss reduce (R7-proven).
// ---------------------------------------------------------------------------
__device__ __forceinline__ void process8(const float4* x, const int* srows, int i,
                                         float4 ck, float& ax, float& ay,
                                         float& az, float& aw,
                                         float invd, float* loss, int l) {
    float s[8];
#pragma unroll
    for (int j = 0; j < 8; j++) {
        float dx = x[j].x - ck.x, dy = x[j].y - ck.y;
        float dz = x[j].z - ck.z, dw = x[j].w - ck.w;
        s[j] = dx * dx + dy * dy + dz * dz + dw * dw;
        ax += x[j].x; ay += x[j].y; az += x[j].z; aw += x[j].w;
    }
    float cc[4];
#pragma unroll
    for (int p = 0; p < 4; p++) {
        float t0 = __shfl_xor_sync(0xFFFFFFFFu, s[2 * p], 16);
        float t1 = __shfl_xor_sync(0xFFFFFFFFu, s[2 * p + 1], 16);
        cc[p] = (l & 16) ? (s[2 * p + 1] + t1) : (s[2 * p] + t0);
    }
    float dd_[2];
#pragma unroll
    for (int p = 0; p < 2; p++) {
        float t0 = __shfl_xor_sync(0xFFFFFFFFu, cc[2 * p], 8);
        float t1 = __shfl_xor_sync(0xFFFFFFFFu, cc[2 * p + 1], 8);
        dd_[p] = (l & 8) ? (cc[2 * p + 1] + t1) : (cc[2 * p] + t0);
    }
    float t0 = __shfl_xor_sync(0xFFFFFFFFu, dd_[0], 4);
    float t1 = __shfl_xor_sync(0xFFFFFFFFu, dd_[1], 4);
    float e  = (l & 4) ? (dd_[1] + t1) : (dd_[0] + t0);
    e += __shfl_xor_sync(0xFFFFFFFFu, e, 2);
    e += __shfl_xor_sync(0xFFFFFFFFu, e, 1);
    if ((l & 3) == 0) {
        int mm = l >> 2;
        int j = ((mm & 1) << 2) | (mm & 2) | (mm >> 2);   // bit-reverse3
        atomicAdd(loss + srows[i + j], e * invd);
    }
}

// ---------------------------------------------------------------------------
// main_k: EXACT R7 body (measured 31.6us): depth-8 register pipeline,
// exclusive g_sx segment store, NO fence, NO arrival counters. Ordering to
// the fold is provided by the reduce_k kernel boundary.
// ---------------------------------------------------------------------------
__global__ void __launch_bounds__(TPB) main_k(const float* __restrict__ X,
                                              const float* __restrict__ C,
                                              float* __restrict__ out) {
    __shared__ int srows[TPB];

    int c   = blockIdx.x;
    int k   = blockIdx.y;
    int seg = blockIdx.z;
    int tid = threadIdx.x;
    int l   = tid & 31;
    int col = c * CHUNK + 4 * tid;

    float4 ck = *reinterpret_cast<const float4*>(C + k * F_ + col);
    float ax = 0.f, ay = 0.f, az = 0.f, aw = 0.f;
    int   cnt  = g_cnt[k];
    float invd = g_invden[k];
    float* loss = out;                          // loss at out[0..N)

    int r0 = (cnt * seg) / S_;
    int r1 = (cnt * (seg + 1)) / S_;
    const int* rl = g_rows + k * N_;

    for (int rb = r0; rb < r1; rb += TPB) {
        int m = min(TPB, r1 - rb);
        if (tid < m) srows[tid] = rl[rb + tid];
        __syncthreads();
        int i = 0;
        if (m >= 8) {
            float4 x[8];
#pragma unroll
            for (int j = 0; j < 8; j++)
                x[j] = *reinterpret_cast<const float4*>(
                    X + (size_t)srows[j] * F_ + col);
#pragma unroll 2
            for (i = 0; i + 16 <= m; i += 8) {
                float4 y[8];
#pragma unroll
                for (int j = 0; j < 8; j++)
                    y[j] = *reinterpret_cast<const float4*>(
                        X + (size_t)srows[i + 8 + j] * F_ + col);
                process8(x, srows, i, ck, ax, ay, az, aw, invd, loss, l);
#pragma unroll
                for (int j = 0; j < 8; j++) x[j] = y[j];
            }
            process8(x, srows, i, ck, ax, ay, az, aw, invd, loss, l);
            i += 8;
        }
        for (; i < m; i++) {                    // tail rows
            float4 x = *reinterpret_cast<const float4*>(
                X + (size_t)srows[i] * F_ + col);
            float dx = x.x - ck.x, dy = x.y - ck.y;
            float dz = x.z - ck.z, dw = x.w - ck.w;
            float s = dx * dx + dy * dy + dz * dz + dw * dw;
            ax += x.x; ay += x.y; az += x.z; aw += x.w;
#pragma unroll
            for (int o = 16; o; o >>= 1)
                s += __shfl_xor_sync(0xFFFFFFFFu, s, o);
            if (l == 0) atomicAdd(loss + srows[i], s * invd);
        }
        __syncthreads();
    }

    // EXCLUSIVE segment-partial store; kernel ends here (no fence).
    *reinterpret_cast<float4*>(g_sx + ((size_t)seg * K_ + k) * F_ + col)
        = make_float4(ax, ay, az, aw);
}

// ---------------------------------------------------------------------------
// reduce_k: fold S_ segment slices + epilogue write of new_cluster. Also
// carries the per-k state resets for graph replay (off main_k's path).
// 256 blocks x 128 threads; 4 blocks per cluster k.
// ---------------------------------------------------------------------------
__global__ void __launch_bounds__(TPB) reduce_k(const float* __restrict__ C,
                                                float* __restrict__ out) {
    int t  = blockIdx.x * TPB + threadIdx.x;    // over K_*F_/4
    int k  = t / (F_ / 4);
    int cv = t % (F_ / 4);
    float4 sum = make_float4(0.f, 0.f, 0.f, 0.f);
#pragma unroll
    for (int s = 0; s < S_; s++) {
        float4 v = __ldcg(reinterpret_cast<const float4*>(
            g_sx + ((size_t)s * K_ + k) * F_) + cv);
        sum.x += v.x; sum.y += v.y; sum.z += v.z; sum.w += v.w;
    }
    float4 ck = reinterpret_cast<const float4*>(C + k * F_)[cv];
    float ga = GAMMA_F * g_ak[k];
    float fc = (float)g_cnt[k];
    float4 o;
    o.x = ck.x - ga * (sum.x - fc * ck.x);
    o.y = ck.y - ga * (sum.y - fc * ck.y);
    o.z = ck.z - ga * (sum.z - fc * ck.z);
    o.w = ck.w - ga * (sum.w - fc * ck.w);
    reinterpret_cast<float4*>(out + N_ + k * F_)[cv] = o;

    // per-k reset for next graph replay: 4 blocks per k; last one resets.
    // (each block spans a single k: F_/4 = 512 elems = 4 blocks of 128)
    if (threadIdx.x == 0) {
        if (atomicAdd(&g_rdone[k], 1) == 3) {
            g_rdone[k] = 0;
            g_cnt[k]   = 0;
            g_rs[k]    = 0.f;
        }
    }
}

extern "C" void kernel_launch(void* const* d_in, const int* in_sizes, int n_in,
                              void* d_out, int out_size) {
    const float* X  = (const float*)d_in[0];   // features [N,F]
    const float* L  = (const float*)d_in[1];   // labels   [N,K] one-hot
    const float* C  = (const float*)d_in[2];   // cluster  [K,F]
    const float* CW = (const float*)d_in[3];   // class_weight [K]
    float* out = (float*)d_out;                // [loss(N) | new_cluster(K*F)]

    setup_k  <<<AB_ + PB_, 256>>>(C, CW, L, out);
    main_k   <<<dim3(NCHUNK, K_, S_), TPB>>>(X, C, out);
    reduce_k <<<(K_ * F_ / 4) / TPB, TPB>>>(C, out);
}